// round 1
// baseline (speedup 1.0000x reference)
#include <cuda_runtime.h>
#include <cstdint>

typedef unsigned long long ull;
typedef unsigned int uint;

constexpr int BH  = 8;     // B*H
constexpr int T   = 512;
constexpr int D   = 64;
constexpr int HID = 128;

// scratch (device globals: no allocation allowed)
__device__ float g_qs[BH*T*HID];   // 2 MB: 0.5*|w2_c| * (q_i . W1q[:,c])
__device__ float g_ks[BH*T*HID];   // 2 MB: 0.5*|w2_c| * (k_j . W1k[:,c] + b1_c)
__device__ float g_Lq[BH*T];       // 0.5 * sum_c w2_c * qh
__device__ float g_Lk[BH*T];       // 0.5 * sum_c w2_c * (kh+b1)
__device__ uint  g_mask[HID];      // sign bit of w2_c
__device__ float g_gc[HID];        // 0.5*|w2_c|

// ---------------- K0: per-channel scale + sign mask ----------------
__global__ void k0_prep(const float* __restrict__ W2) {
    int c = threadIdx.x;
    float w = W2[c];
    g_mask[c] = __float_as_uint(w) & 0x80000000u;
    g_gc[c]   = 0.5f * fabsf(w);
}

// ---------------- K1: projections, scaled + bias-folded ----------------
// grid (8 rowchunks, BH, 2[q/k]), 256 threads. smem: W part 32KB + rows 16KB = 48KB.
__global__ __launch_bounds__(256) void k1_proj(
    const float* __restrict__ q, const float* __restrict__ k,
    const float* __restrict__ W1, const float* __restrict__ b1)
{
    __shared__ float sW[D][HID];
    __shared__ float sR[64][D];
    int tid   = threadIdx.x;
    int bh    = blockIdx.y;
    int r0    = blockIdx.x * 64;
    int isk   = blockIdx.z;

    const float* src  = isk ? k : q;
    const float* wsrc = W1 + (isk ? D * HID : 0);

    for (int idx = tid; idx < D*HID/4; idx += 256) {
        int r = idx >> 5, c = idx & 31;
        *(float4*)&sW[r][c*4] = *(const float4*)&wsrc[r*HID + c*4];
    }
    for (int idx = tid; idx < 64*D/4; idx += 256) {
        int r = idx >> 4, c = idx & 15;
        *(float4*)&sR[r][c*4] = *(const float4*)&src[(bh*T + r0 + r)*D + c*4];
    }
    __syncthreads();

    int ti = tid >> 4;      // 0..15 -> 4 rows each
    int tc = tid & 15;      // 8 channels each
    int c0 = tc * 8;

    ull acc[4][4];
    #pragma unroll
    for (int a = 0; a < 4; a++)
        #pragma unroll
        for (int b = 0; b < 4; b++) acc[a][b] = 0ull;

    #pragma unroll 2
    for (int d = 0; d < D; d++) {
        const ull* pw = (const ull*)&sW[d][c0];
        ull w0 = pw[0], w1 = pw[1], w2 = pw[2], w3 = pw[3];
        #pragma unroll
        for (int ii = 0; ii < 4; ii++) {
            float a = sR[ti*4 + ii][d];
            ull ap; asm("mov.b64 %0, {%1,%1};" : "=l"(ap) : "f"(a));
            asm("fma.rn.f32x2 %0, %1, %2, %0;" : "+l"(acc[ii][0]) : "l"(ap), "l"(w0));
            asm("fma.rn.f32x2 %0, %1, %2, %0;" : "+l"(acc[ii][1]) : "l"(ap), "l"(w1));
            asm("fma.rn.f32x2 %0, %1, %2, %0;" : "+l"(acc[ii][2]) : "l"(ap), "l"(w2));
            asm("fma.rn.f32x2 %0, %1, %2, %0;" : "+l"(acc[ii][3]) : "l"(ap), "l"(w3));
        }
    }

    float* dst = (isk ? g_ks : g_qs) + (bh*T + r0) * HID;
    float gg[8], bb[8];
    #pragma unroll
    for (int c = 0; c < 8; c++) { gg[c] = g_gc[c0+c]; bb[c] = isk ? b1[c0+c] : 0.0f; }

    #pragma unroll
    for (int ii = 0; ii < 4; ii++) {
        float v[8];
        #pragma unroll
        for (int p = 0; p < 4; p++) {
            v[2*p]   = __uint_as_float((uint)(acc[ii][p] & 0xffffffffu));
            v[2*p+1] = __uint_as_float((uint)(acc[ii][p] >> 32));
        }
        float o[8];
        #pragma unroll
        for (int c = 0; c < 8; c++) o[c] = gg[c] * (v[c] + bb[c]);
        int row = ti*4 + ii;
        *(float4*)&dst[row*HID + c0]     = make_float4(o[0], o[1], o[2], o[3]);
        *(float4*)&dst[row*HID + c0 + 4] = make_float4(o[4], o[5], o[6], o[7]);
    }
}

// ---------------- K2: linear-term row sums Lq/Lk ----------------
__global__ __launch_bounds__(256) void k2_lin() {
    int gw   = (blockIdx.x * 256 + threadIdx.x) >> 5;  // 0..2047
    int lane = threadIdx.x & 31;
    uint4 m  = *(const uint4*)&g_mask[lane*4];
    #pragma unroll
    for (int rr = 0; rr < 4; rr++) {
        int row = gw*4 + rr;              // 0..8191, first 4096 = q side
        bool isk = row >= BH*T;
        int r = isk ? row - BH*T : row;
        const float* src = (isk ? g_ks : g_qs) + r*HID + lane*4;
        float4 v = *(const float4*)src;
        float s = __uint_as_float(__float_as_uint(v.x) ^ m.x)
                + __uint_as_float(__float_as_uint(v.y) ^ m.y)
                + __uint_as_float(__float_as_uint(v.z) ^ m.z)
                + __uint_as_float(__float_as_uint(v.w) ^ m.w);
        #pragma unroll
        for (int o = 16; o; o >>= 1) s += __shfl_xor_sync(0xffffffffu, s, o);
        if (lane == 0) { if (isk) g_Lk[r] = s; else g_Lq[r] = s; }
    }
}

// ---------------- K3: pairwise |.| main kernel ----------------
constexpr int PAD = 132;                                   // bank-conflict padding
constexpr int SM3_BYTES = (64*PAD + 256*PAD + 128) * 4;    // ~169.5 KB

__global__ __launch_bounds__(512, 1) void k3_main(
    const float* __restrict__ b2, float* __restrict__ out)
{
    extern __shared__ float smem[];
    float* sq    = smem;                     // [64][PAD]
    float* sk    = smem + 64*PAD;            // [256][PAD]
    uint*  smask = (uint*)(smem + 64*PAD + 256*PAD);

    int tid = threadIdx.x;
    int bx  = blockIdx.x;
    int bh  = bx >> 4;
    int it  = (bx >> 1) & 7;
    int jt  = bx & 1;
    int i0  = it * 64, j0 = jt * 256;

    const float* gq = g_qs + (size_t)(bh*T + i0) * HID;
    for (int idx = tid; idx < 64*32; idx += 512) {
        int r = idx >> 5, c = idx & 31;
        *(float4*)&sq[r*PAD + c*4] = *(const float4*)&gq[r*HID + c*4];
    }
    const float* gk = g_ks + (size_t)(bh*T + j0) * HID;
    for (int idx = tid; idx < 256*32; idx += 512) {
        int r = idx >> 5, c = idx & 31;
        *(float4*)&sk[r*PAD + c*4] = *(const float4*)&gk[r*HID + c*4];
    }
    if (tid < 128) smask[tid] = g_mask[tid];
    __syncthreads();

    int warp = tid >> 5, lane = tid & 31;
    int wi = warp >> 3, wj = warp & 7;     // warps 2x8 over (i,j)
    int li = lane >> 3, lj = lane & 7;     // lanes 4x8 over (i,j)

    const float* qb = sq + (wi*32 + li) * PAD;  // thread rows: +4*r
    const float* kb = sk + (wj*32 + lj) * PAD;  // thread cols: +8*s

    ull acc[8][4];
    #pragma unroll
    for (int r = 0; r < 8; r++)
        #pragma unroll
        for (int s = 0; s < 4; s++) acc[r][s] = 0ull;

    for (int c = 0; c < HID; c += 2) {
        ull qv[8], kv[4];
        #pragma unroll
        for (int r = 0; r < 8; r++) qv[r] = *(const ull*)(qb + r*4*PAD + c);
        #pragma unroll
        for (int s = 0; s < 4; s++) kv[s] = *(const ull*)(kb + s*8*PAD + c);
        uint m0 = smask[c], m1 = smask[c+1];
        #pragma unroll
        for (int r = 0; r < 8; r++)
            #pragma unroll
            for (int s = 0; s < 4; s++) {
                // t = qv+kv (f32x2); signed-abs via single LOP3 per half; acc += (f32x2)
                asm("{\n\t"
                    ".reg .b64 t;\n\t"
                    ".reg .b32 lo, hi;\n\t"
                    "add.rn.f32x2 t, %1, %2;\n\t"
                    "mov.b64 {lo, hi}, t;\n\t"
                    "lop3.b32 lo, lo, 0x7fffffff, %3, 0x6A;\n\t"
                    "lop3.b32 hi, hi, 0x7fffffff, %4, 0x6A;\n\t"
                    "mov.b64 t, {lo, hi};\n\t"
                    "add.rn.f32x2 %0, %0, t;\n\t"
                    "}"
                    : "+l"(acc[r][s]) : "l"(qv[r]), "l"(kv[s]), "r"(m0), "r"(m1));
            }
    }

    float b2v = b2[0];
    float Lqr[8], Lks[4];
    #pragma unroll
    for (int r = 0; r < 8; r++) Lqr[r] = g_Lq[bh*T + i0 + wi*32 + li + 4*r] + b2v;
    #pragma unroll
    for (int s = 0; s < 4; s++) Lks[s] = g_Lk[bh*T + j0 + wj*32 + lj + 8*s];

    float* ob = out + (size_t)(bh*T + i0 + wi*32 + li) * T + j0 + wj*32 + lj;
    #pragma unroll
    for (int r = 0; r < 8; r++)
        #pragma unroll
        for (int s = 0; s < 4; s++) {
            float lo = __uint_as_float((uint)(acc[r][s] & 0xffffffffu));
            float hi = __uint_as_float((uint)(acc[r][s] >> 32));
            ob[(size_t)(4*r)*T + 8*s] = lo + hi + Lqr[r] + Lks[s];
        }
}

// ---------------- launch ----------------
extern "C" void kernel_launch(void* const* d_in, const int* in_sizes, int n_in,
                              void* d_out, int out_size) {
    const float* q  = (const float*)d_in[0];
    const float* k  = (const float*)d_in[1];
    const float* W1 = (const float*)d_in[2];
    const float* b1 = (const float*)d_in[3];
    const float* W2 = (const float*)d_in[4];
    const float* b2 = (const float*)d_in[5];
    float* out = (float*)d_out;

    cudaFuncSetAttribute(k3_main, cudaFuncAttributeMaxDynamicSharedMemorySize, SM3_BYTES);

    k0_prep<<<1, HID>>>(W2);
    k1_proj<<<dim3(8, BH, 2), 256>>>(q, k, W1, b1);
    k2_lin<<<256, 256>>>();
    k3_main<<<128, 512, SM3_BYTES>>>(b2, out);
}

// round 2
// speedup vs baseline: 1.1072x; 1.1072x over previous
#include <cuda_runtime.h>
#include <cstdint>

typedef unsigned long long ull;
typedef unsigned int uint;

constexpr int BH  = 8;
constexpr int T   = 512;
constexpr int D   = 64;
constexpr int HID = 128;
constexpr int NP  = HID / 2;   // 64 channel pairs

// pair-major scratch: [bh][pair][T] as 64-bit channel pairs
__device__ ull   g_qsp[BH * NP * T];   // 2 MB
__device__ ull   g_ksp[BH * NP * T];   // 2 MB
__device__ float g_Lq[BH * T];
__device__ float g_Lk[BH * T];
__device__ uint  g_mask[HID];
__device__ ull   g_maskp[NP];
__device__ float g_gc[HID];

// ---------------- K0: per-channel scale + sign masks ----------------
__global__ void k0_prep(const float* __restrict__ W2) {
    int c = threadIdx.x;
    float w = W2[c];
    g_mask[c] = __float_as_uint(w) & 0x80000000u;
    g_gc[c]   = 0.5f * fabsf(w);
    if (c < NP) {
        uint m0 = __float_as_uint(W2[2 * c])     & 0x80000000u;
        uint m1 = __float_as_uint(W2[2 * c + 1]) & 0x80000000u;
        g_maskp[c] = (ull)m0 | ((ull)m1 << 32);
    }
}

// ---------------- K1: projections + linear row sums + pair-major transpose ----------------
// smem: sWp [64][64] ull (32KB) | sR [64][68] float (17.4KB); sT [64][65] ull aliases at 0.
constexpr int SM1_BYTES = 32768 + 64 * 68 * 4;   // 50176

__global__ __launch_bounds__(256) void k1_proj(
    const float* __restrict__ q, const float* __restrict__ k,
    const float* __restrict__ W1, const float* __restrict__ b1)
{
    extern __shared__ char sm1[];
    ull*   sWp = (ull*)sm1;               // [D][NP]
    float* sR  = (float*)(sm1 + 32768);   // [64][68]
    ull*   sT  = (ull*)sm1;               // [64][65] (aliased after sync)

    int tid = threadIdx.x;
    int bh  = blockIdx.y;
    int r0  = blockIdx.x * 64;
    int isk = blockIdx.z;

    const float* src  = isk ? k : q;
    const float* wsrc = W1 + (isk ? D * HID : 0);

    // fill weight pairs: float4 covers pairs 2g, 2g+1 (layout-identical)
    for (int idx = tid; idx < D * HID / 4; idx += 256) {
        int d = idx >> 5, g = idx & 31;
        *(float4*)&sWp[d * NP + 2 * g] = *(const float4*)&wsrc[d * HID + g * 4];
    }
    for (int idx = tid; idx < 64 * D / 4; idx += 256) {
        int r = idx >> 4, c = idx & 15;
        *(float4*)&sR[r * 68 + c * 4] = *(const float4*)&src[(bh * T + r0 + r) * D + c * 4];
    }
    __syncthreads();

    int ti = tid >> 4;      // 16 groups x 4 rows
    int tc = tid & 15;      // pairs {tc, tc+16, tc+32, tc+48}

    ull acc[4][4];
    #pragma unroll
    for (int a = 0; a < 4; a++)
        #pragma unroll
        for (int b = 0; b < 4; b++) acc[a][b] = 0ull;

    #pragma unroll 2
    for (int d = 0; d < D; d++) {
        ull w0 = sWp[d * NP + tc];
        ull w1 = sWp[d * NP + tc + 16];
        ull w2 = sWp[d * NP + tc + 32];
        ull w3 = sWp[d * NP + tc + 48];
        #pragma unroll
        for (int ii = 0; ii < 4; ii++) {
            float a = sR[(ti * 4 + ii) * 68 + d];
            ull ap; asm("mov.b64 %0, {%1,%1};" : "=l"(ap) : "f"(a));
            asm("fma.rn.f32x2 %0, %1, %2, %0;" : "+l"(acc[ii][0]) : "l"(ap), "l"(w0));
            asm("fma.rn.f32x2 %0, %1, %2, %0;" : "+l"(acc[ii][1]) : "l"(ap), "l"(w1));
            asm("fma.rn.f32x2 %0, %1, %2, %0;" : "+l"(acc[ii][2]) : "l"(ap), "l"(w2));
            asm("fma.rn.f32x2 %0, %1, %2, %0;" : "+l"(acc[ii][3]) : "l"(ap), "l"(w3));
        }
    }

    // per-channel params (channels 2*(tc+16m)+e)
    float gg[8], bb[8]; uint mk[8];
    #pragma unroll
    for (int m = 0; m < 4; m++)
        #pragma unroll
        for (int e = 0; e < 2; e++) {
            int ch = 2 * (tc + 16 * m) + e;
            gg[2 * m + e] = g_gc[ch];
            bb[2 * m + e] = isk ? b1[ch] : 0.0f;
            mk[2 * m + e] = g_mask[ch];
        }

    __syncthreads();   // sW/sR dead; sT may alias now

    float ls[4];
    #pragma unroll
    for (int ii = 0; ii < 4; ii++) {
        float o[8];
        #pragma unroll
        for (int m = 0; m < 4; m++) {
            float lo = __uint_as_float((uint)(acc[ii][m] & 0xffffffffu));
            float hi = __uint_as_float((uint)(acc[ii][m] >> 32));
            o[2 * m]     = gg[2 * m]     * (lo + bb[2 * m]);
            o[2 * m + 1] = gg[2 * m + 1] * (hi + bb[2 * m + 1]);
            ull pr = (ull)__float_as_uint(o[2 * m]) | ((ull)__float_as_uint(o[2 * m + 1]) << 32);
            sT[(ti * 4 + ii) * 65 + tc + 16 * m] = pr;
        }
        float s = 0.0f;
        #pragma unroll
        for (int c = 0; c < 8; c++)
            s += __uint_as_float(__float_as_uint(o[c]) ^ mk[c]);
        ls[ii] = s;
    }
    // reduce linear sums over the 16-thread tc group
    #pragma unroll
    for (int ii = 0; ii < 4; ii++) {
        float s = ls[ii];
        #pragma unroll
        for (int off = 8; off; off >>= 1) s += __shfl_xor_sync(0xffffffffu, s, off);
        if (tc == 0) {
            int row = bh * T + r0 + ti * 4 + ii;
            if (isk) g_Lk[row] = s; else g_Lq[row] = s;
        }
    }
    __syncthreads();

    // coalesced pair-major writeout
    ull* dst = (isk ? g_ksp : g_qsp) + (size_t)bh * NP * T;
    for (int idx = tid; idx < 64 * NP; idx += 256) {
        int r = idx & 63, p = idx >> 6;
        dst[p * T + r0 + r] = sT[r * 65 + p];
    }
}

// ---------------- K3: pairwise |.| main kernel (pair-major, conflict-free) ----------------
constexpr int SM3_BYTES = NP * 64 * 8 + NP * 256 * 8 + NP * 8;   // 164352

__global__ __launch_bounds__(512, 1) void k3_main(
    const float* __restrict__ b2, float* __restrict__ out)
{
    extern __shared__ ull sm3[];
    ull* sq  = sm3;              // [p][64 rows]
    ull* sk  = sq + NP * 64;     // [p][256 rows]
    ull* smk = sk + NP * 256;    // [64]

    int tid = threadIdx.x;
    int bx  = blockIdx.x;
    int bh  = bx >> 4;
    int it  = (bx >> 1) & 7;
    int jt  = bx & 1;
    int i0  = it * 64, j0 = jt * 256;

    const ull* gq = g_qsp + (size_t)bh * NP * T;
    const ull* gk = g_ksp + (size_t)bh * NP * T;

    for (int idx = tid; idx < NP * 64; idx += 512) {
        int p = idx >> 6, r = idx & 63;
        sq[idx] = gq[p * T + i0 + r];
    }
    for (int idx = tid; idx < NP * 256; idx += 512) {
        int p = idx >> 8, r = idx & 255;
        sk[idx] = gk[p * T + j0 + r];
    }
    if (tid < NP) smk[tid] = g_maskp[tid];
    __syncthreads();

    int warp = tid >> 5, lane = tid & 31;
    int wi = warp >> 3, wj = warp & 7;   // 2x8 warps over (i,j)
    int li = lane >> 3, lj = lane & 7;   // 4x8 lanes

    const ull* qb = sq + wi * 32 + li;   // + 4r + 64p
    const ull* kb = sk + wj * 32 + lj;   // + 8s + 256p

    ull acc[8][4];
    #pragma unroll
    for (int r = 0; r < 8; r++)
        #pragma unroll
        for (int s = 0; s < 4; s++) acc[r][s] = 0ull;

    #pragma unroll 1
    for (int p = 0; p < NP; p++) {
        ull qv[8], kv[4];
        #pragma unroll
        for (int r = 0; r < 8; r++) qv[r] = qb[p * 64 + 4 * r];
        #pragma unroll
        for (int s = 0; s < 4; s++) kv[s] = kb[p * 256 + 8 * s];
        ull mp = smk[p];
        uint m0 = (uint)(mp & 0xffffffffu), m1 = (uint)(mp >> 32);
        #pragma unroll
        for (int r = 0; r < 8; r++)
            #pragma unroll
            for (int s = 0; s < 4; s++) {
                asm("{\n\t"
                    ".reg .b64 t;\n\t"
                    ".reg .b32 lo, hi;\n\t"
                    "add.rn.f32x2 t, %1, %2;\n\t"
                    "mov.b64 {lo, hi}, t;\n\t"
                    "lop3.b32 lo, lo, 0x7fffffff, %3, 0x6A;\n\t"
                    "lop3.b32 hi, hi, 0x7fffffff, %4, 0x6A;\n\t"
                    "mov.b64 t, {lo, hi};\n\t"
                    "add.rn.f32x2 %0, %0, t;\n\t"
                    "}"
                    : "+l"(acc[r][s]) : "l"(qv[r]), "l"(kv[s]), "r"(m0), "r"(m1));
            }
    }

    float b2v = b2[0];
    float Lqr[8], Lks[4];
    #pragma unroll
    for (int r = 0; r < 8; r++) Lqr[r] = g_Lq[bh * T + i0 + wi * 32 + li + 4 * r] + b2v;
    #pragma unroll
    for (int s = 0; s < 4; s++) Lks[s] = g_Lk[bh * T + j0 + wj * 32 + lj + 8 * s];

    float* ob = out + (size_t)(bh * T + i0 + wi * 32 + li) * T + j0 + wj * 32 + lj;
    #pragma unroll
    for (int r = 0; r < 8; r++)
        #pragma unroll
        for (int s = 0; s < 4; s++) {
            float lo = __uint_as_float((uint)(acc[r][s] & 0xffffffffu));
            float hi = __uint_as_float((uint)(acc[r][s] >> 32));
            ob[(size_t)(4 * r) * T + 8 * s] = lo + hi + Lqr[r] + Lks[s];
        }
}

// ---------------- launch ----------------
extern "C" void kernel_launch(void* const* d_in, const int* in_sizes, int n_in,
                              void* d_out, int out_size) {
    const float* q  = (const float*)d_in[0];
    const float* k  = (const float*)d_in[1];
    const float* W1 = (const float*)d_in[2];
    const float* b1 = (const float*)d_in[3];
    const float* W2 = (const float*)d_in[4];
    const float* b2 = (const float*)d_in[5];
    float* out = (float*)d_out;

    cudaFuncSetAttribute(k1_proj, cudaFuncAttributeMaxDynamicSharedMemorySize, SM1_BYTES);
    cudaFuncSetAttribute(k3_main, cudaFuncAttributeMaxDynamicSharedMemorySize, SM3_BYTES);

    k0_prep<<<1, HID>>>(W2);
    k1_proj<<<dim3(8, BH, 2), 256, SM1_BYTES>>>(q, k, W1, b1);
    k3_main<<<128, 512, SM3_BYTES>>>(b2, out);
}

// round 4
// speedup vs baseline: 1.4432x; 1.3035x over previous
#include <cuda_runtime.h>
#include <cstdint>

typedef unsigned long long ull;
typedef unsigned int uint;

constexpr int BH  = 8;
constexpr int T   = 512;
constexpr int D   = 64;
constexpr int HID = 128;
constexpr int NP  = HID / 2;   // 64 channel pairs

// pair-major scratch: [bh][pair][T] as 64-bit channel pairs, |w2| folded, b1 folded into k
__device__ ull g_qsp[BH * NP * T];   // 2 MB
__device__ ull g_ksp[BH * NP * T];   // 2 MB

// ---------------- K1: projections (|w2| and b1 folded) + pair-major transpose ----------------
// smem: sWp [64][64] ull (32KB) | sR [64][68] float (17.4KB); sT [64][65] ull aliases at 0.
constexpr int SM1_BYTES = 32768 + 64 * 68 * 4;   // 50176

__global__ __launch_bounds__(256) void k1_proj(
    const float* __restrict__ q, const float* __restrict__ k,
    const float* __restrict__ W1, const float* __restrict__ b1,
    const float* __restrict__ W2)
{
    extern __shared__ char sm1[];
    ull*   sWp = (ull*)sm1;               // [D][NP]
    float* sR  = (float*)(sm1 + 32768);   // [64][68]
    ull*   sT  = (ull*)sm1;               // [64][65] (aliased after sync)

    int tid = threadIdx.x;
    int bh  = blockIdx.y;
    int r0  = blockIdx.x * 64;
    int isk = blockIdx.z;

    const float* src  = isk ? k : q;
    const float* wsrc = W1 + (isk ? D * HID : 0);

    for (int idx = tid; idx < D * HID / 4; idx += 256) {
        int d = idx >> 5, g = idx & 31;
        *(float4*)&sWp[d * NP + 2 * g] = *(const float4*)&wsrc[d * HID + g * 4];
    }
    for (int idx = tid; idx < 64 * D / 4; idx += 256) {
        int r = idx >> 4, c = idx & 15;
        *(float4*)&sR[r * 68 + c * 4] = *(const float4*)&src[(bh * T + r0 + r) * D + c * 4];
    }
    __syncthreads();

    int ti = tid >> 4;      // 16 groups x 4 rows
    int tc = tid & 15;      // pairs {tc, tc+16, tc+32, tc+48}

    ull acc[4][4];
    #pragma unroll
    for (int a = 0; a < 4; a++)
        #pragma unroll
        for (int b = 0; b < 4; b++) acc[a][b] = 0ull;

    #pragma unroll 2
    for (int d = 0; d < D; d++) {
        ull w0 = sWp[d * NP + tc];
        ull w1 = sWp[d * NP + tc + 16];
        ull w2 = sWp[d * NP + tc + 32];
        ull w3 = sWp[d * NP + tc + 48];
        #pragma unroll
        for (int ii = 0; ii < 4; ii++) {
            float a = sR[(ti * 4 + ii) * 68 + d];
            ull ap; asm("mov.b64 %0, {%1,%1};" : "=l"(ap) : "f"(a));
            asm("fma.rn.f32x2 %0, %1, %2, %0;" : "+l"(acc[ii][0]) : "l"(ap), "l"(w0));
            asm("fma.rn.f32x2 %0, %1, %2, %0;" : "+l"(acc[ii][1]) : "l"(ap), "l"(w1));
            asm("fma.rn.f32x2 %0, %1, %2, %0;" : "+l"(acc[ii][2]) : "l"(ap), "l"(w2));
            asm("fma.rn.f32x2 %0, %1, %2, %0;" : "+l"(acc[ii][3]) : "l"(ap), "l"(w3));
        }
    }

    // per-channel params: gg = |w2_c|, bb = b1 (k side only); channels 2*(tc+16m)+e
    float gg[8], bb[8];
    #pragma unroll
    for (int m = 0; m < 4; m++)
        #pragma unroll
        for (int e = 0; e < 2; e++) {
            int ch = 2 * (tc + 16 * m) + e;
            gg[2 * m + e] = fabsf(W2[ch]);
            bb[2 * m + e] = isk ? b1[ch] : 0.0f;
        }

    __syncthreads();   // sW/sR dead; sT may alias now

    #pragma unroll
    for (int ii = 0; ii < 4; ii++) {
        #pragma unroll
        for (int m = 0; m < 4; m++) {
            float lo = __uint_as_float((uint)(acc[ii][m] & 0xffffffffu));
            float hi = __uint_as_float((uint)(acc[ii][m] >> 32));
            float o0 = gg[2 * m]     * (lo + bb[2 * m]);
            float o1 = gg[2 * m + 1] * (hi + bb[2 * m + 1]);
            ull pr = (ull)__float_as_uint(o0) | ((ull)__float_as_uint(o1) << 32);
            sT[(ti * 4 + ii) * 65 + tc + 16 * m] = pr;
        }
    }
    __syncthreads();

    // coalesced pair-major writeout
    ull* dst = (isk ? g_ksp : g_qsp) + (size_t)bh * NP * T;
    for (int idx = tid; idx < 64 * NP; idx += 256) {
        int r = idx & 63, p = idx >> 6;
        dst[p * T + r0 + r] = sT[r * 65 + p];
    }
}

// ---------------- K3: pairwise relu main kernel (scalar-max form, 1024 threads) ----------------
constexpr int SM3_BYTES = NP * 64 * 8 + NP * 256 * 8 + NP * 8;   // 164352

__global__ __launch_bounds__(1024, 1) void k3_main(
    const float* __restrict__ W2, const float* __restrict__ b2,
    float* __restrict__ out)
{
    extern __shared__ ull sm3[];
    ull* sq  = sm3;              // [p][64 rows]
    ull* sk  = sq + NP * 64;     // [p][256 rows]
    ull* ssg = sk + NP * 256;    // [64] packed (+-1.0f, +-1.0f)

    int tid = threadIdx.x;
    int bx  = blockIdx.x;
    int bh  = bx >> 4;
    int it  = (bx >> 1) & 7;
    int jt  = bx & 1;
    int i0  = it * 64, j0 = jt * 256;

    const ull* gq = g_qsp + (size_t)bh * NP * T;
    const ull* gk = g_ksp + (size_t)bh * NP * T;

    for (int idx = tid; idx < NP * 64; idx += 1024) {
        int p = idx >> 6, r = idx & 63;
        sq[idx] = gq[p * T + i0 + r];
    }
    for (int idx = tid; idx < NP * 256; idx += 1024) {
        int p = idx >> 8, r = idx & 255;
        sk[idx] = gk[p * T + j0 + r];
    }
    if (tid < NP) {
        uint s0 = 0x3F800000u | (__float_as_uint(W2[2 * tid])     & 0x80000000u);
        uint s1 = 0x3F800000u | (__float_as_uint(W2[2 * tid + 1]) & 0x80000000u);
        ssg[tid] = (ull)s0 | ((ull)s1 << 32);
    }
    __syncthreads();

    int warp = tid >> 5, lane = tid & 31;
    int wi = warp >> 3, wj = warp & 7;   // 4x8 warps over (i,j)
    int li = lane >> 3, lj = lane & 7;   // 4x8 lanes

    const ull* qb = sq + wi * 16 + li;   // rows: + 4r, pairs: + 64p
    const ull* kb = sk + wj * 32 + lj;   // cols: + 8s, pairs: + 256p

    ull acc[4][4];
    #pragma unroll
    for (int r = 0; r < 4; r++)
        #pragma unroll
        for (int s = 0; s < 4; s++) acc[r][s] = 0ull;

    #pragma unroll 1
    for (int p = 0; p < NP; p++) {
        ull qv[4], kv[4];
        #pragma unroll
        for (int r = 0; r < 4; r++) qv[r] = qb[p * 64 + 4 * r];
        #pragma unroll
        for (int s = 0; s < 4; s++) kv[s] = kb[p * 256 + 8 * s];
        ull sg = ssg[p];
        #pragma unroll
        for (int r = 0; r < 4; r++)
            #pragma unroll
            for (int s = 0; s < 4; s++) {
                // u = q+k (packed); relu each half (FMNMX, alu pipe); acc += u * (+-1) (packed)
                asm("{\n\t"
                    ".reg .b64 t;\n\t"
                    ".reg .f32 lo, hi;\n\t"
                    "add.rn.f32x2 t, %1, %2;\n\t"
                    "mov.b64 {lo, hi}, t;\n\t"
                    "max.f32 lo, lo, 0f00000000;\n\t"
                    "max.f32 hi, hi, 0f00000000;\n\t"
                    "mov.b64 t, {lo, hi};\n\t"
                    "fma.rn.f32x2 %0, t, %3, %0;\n\t"
                    "}"
                    : "+l"(acc[r][s]) : "l"(qv[r]), "l"(kv[s]), "l"(sg));
            }
    }

    float b2v = b2[0];
    float* ob = out + (size_t)(bh * T + i0 + wi * 16 + li) * T + j0 + wj * 32 + lj;
    #pragma unroll
    for (int r = 0; r < 4; r++)
        #pragma unroll
        for (int s = 0; s < 4; s++) {
            float lo = __uint_as_float((uint)(acc[r][s] & 0xffffffffu));
            float hi = __uint_as_float((uint)(acc[r][s] >> 32));
            ob[(size_t)(4 * r) * T + 8 * s] = lo + hi + b2v;
        }
}

// ---------------- launch ----------------
extern "C" void kernel_launch(void* const* d_in, const int* in_sizes, int n_in,
                              void* d_out, int out_size) {
    const float* q  = (const float*)d_in[0];
    const float* k  = (const float*)d_in[1];
    const float* W1 = (const float*)d_in[2];
    const float* b1 = (const float*)d_in[3];
    const float* W2 = (const float*)d_in[4];
    const float* b2 = (const float*)d_in[5];
    float* out = (float*)d_out;

    cudaFuncSetAttribute(k1_proj, cudaFuncAttributeMaxDynamicSharedMemorySize, SM1_BYTES);
    cudaFuncSetAttribute(k3_main, cudaFuncAttributeMaxDynamicSharedMemorySize, SM3_BYTES);

    k1_proj<<<dim3(8, BH, 2), 256, SM1_BYTES>>>(q, k, W1, b1, W2);
    k3_main<<<128, 1024, SM3_BYTES>>>(W2, b2, out);
}